// round 14
// baseline (speedup 1.0000x reference)
#include <cuda_runtime.h>

#define NPTS  12000
#define DIN   64
#define DLAT  16
#define DFEAT 64
#define KNN   16
#define NCHUNK 3
#define TI    128          // i-tile (queries per block)
#define TJ    128          // j-tile
#define NT    94           // ceil(NPTS/TJ)
#define TPC   32           // tiles per chunk (last chunk: 30)
#define D2S   (TJ + 4)     // padded d2 row stride (words)
#define QWARP 4            // queries per warp in out_kernel

// select smem: sA + sB + sqI + sqJ + sD2
#define SMEM_SEL ((2 * DLAT * TI + 2 * TI + TI * D2S) * 4)

// ---------------- scratch ----------------
__device__ float g_coords[NPTS * DLAT];
__device__ float g_sq[NPTS];
__device__ float g_feats[NPTS * DFEAT];
__device__ float g_td[NPTS * NCHUNK * KNN];
__device__ int   g_ti[NPTS * NCHUNK * KNN];
__device__ float g_w[NPTS * KNN];
__device__ int   g_idx[NPTS * KNN];

__device__ __forceinline__ float finf()  { return __int_as_float(0x7f800000); }
__device__ __forceinline__ float fninf() { return __int_as_float(0xff800000); }

// ---------------- kernel 1: encoders ----------------
__global__ void __launch_bounds__(64) encode_kernel(
    const float* __restrict__ x,
    const float* __restrict__ Wf, const float* __restrict__ bf,
    const float* __restrict__ Wl, const float* __restrict__ bl)
{
    __shared__ float sxT[DIN * 64];
    __shared__ float sWf[DIN * DFEAT];
    __shared__ float sWl[DIN * DLAT];
    __shared__ float sbf[DFEAT];
    __shared__ float sbl[DLAT];

    const int tid = threadIdx.x;
    const int i0  = blockIdx.x * 64;

    for (int e = tid; e < DIN * DFEAT; e += 64) sWf[e] = Wf[e];
    for (int e = tid; e < DIN * DLAT;  e += 64) sWl[e] = Wl[e];
    if (tid < DFEAT) sbf[tid] = bf[tid];
    if (tid < DLAT)  sbl[tid] = bl[tid];

    const float4* x4 = (const float4*)x;
    for (int e = tid; e < 64 * (DIN / 4); e += 64) {
        int r = e >> 4, c4 = e & 15;
        float4 v = make_float4(0.f, 0.f, 0.f, 0.f);
        if (i0 + r < NPTS) v = x4[(size_t)(i0 + r) * (DIN / 4) + c4];
        sxT[(4 * c4 + 0) * 64 + r] = v.x;
        sxT[(4 * c4 + 1) * 64 + r] = v.y;
        sxT[(4 * c4 + 2) * 64 + r] = v.z;
        sxT[(4 * c4 + 3) * 64 + r] = v.w;
    }
    __syncthreads();

    const int i = i0 + tid;
    if (i >= NPTS) return;

    for (int ft = 0; ft < DFEAT; ft += 16) {
        float acc[16];
        #pragma unroll
        for (int f = 0; f < 16; f++) acc[f] = sbf[ft + f];
        #pragma unroll 4
        for (int k = 0; k < DIN; k++) {
            float xv = sxT[k * 64 + tid];
            const float4* wr = (const float4*)(sWf + k * DFEAT + ft);
            #pragma unroll
            for (int q = 0; q < 4; q++) {
                float4 w = wr[q];
                acc[4*q+0] = fmaf(xv, w.x, acc[4*q+0]);
                acc[4*q+1] = fmaf(xv, w.y, acc[4*q+1]);
                acc[4*q+2] = fmaf(xv, w.z, acc[4*q+2]);
                acc[4*q+3] = fmaf(xv, w.w, acc[4*q+3]);
            }
        }
        float4* fo = (float4*)(g_feats + (size_t)i * DFEAT + ft);
        #pragma unroll
        for (int q = 0; q < 4; q++)
            fo[q] = make_float4(tanhf(acc[4*q+0]), tanhf(acc[4*q+1]),
                                tanhf(acc[4*q+2]), tanhf(acc[4*q+3]));
    }

    {
        float acc[16];
        #pragma unroll
        for (int f = 0; f < 16; f++) acc[f] = sbl[f];
        #pragma unroll 4
        for (int k = 0; k < DIN; k++) {
            float xv = sxT[k * 64 + tid];
            const float4* wr = (const float4*)(sWl + k * DLAT);
            #pragma unroll
            for (int q = 0; q < 4; q++) {
                float4 w = wr[q];
                acc[4*q+0] = fmaf(xv, w.x, acc[4*q+0]);
                acc[4*q+1] = fmaf(xv, w.y, acc[4*q+1]);
                acc[4*q+2] = fmaf(xv, w.z, acc[4*q+2]);
                acc[4*q+3] = fmaf(xv, w.w, acc[4*q+3]);
            }
        }
        float sq = 0.f;
        float4* co = (float4*)(g_coords + (size_t)i * DLAT);
        #pragma unroll
        for (int q = 0; q < 4; q++) {
            float t0 = tanhf(acc[4*q+0]);
            float t1 = tanhf(acc[4*q+1]);
            float t2 = tanhf(acc[4*q+2]);
            float t3 = tanhf(acc[4*q+3]);
            co[q] = make_float4(t0, t1, t2, t3);
            sq += t0*t0 + t1*t1 + t2*t2 + t3*t3;
        }
        g_sq[i] = sq;
    }
}

// ---------------- kernel 2: R2 tiled distance GEMM + float4-scan top-16 ----------------
__global__ void __launch_bounds__(256, 2) select_kernel()
{
    extern __shared__ float sm[];
    float* sA  = sm;                       // [16][128] coords_i transposed
    float* sB  = sm + DLAT * TI;           // [16][128] 2*coords_j transposed
    float* sqI = sm + 2 * DLAT * TI;       // [128]
    float* sqJ = sqI + TI;                 // [128]
    float* sD2 = sqJ + TJ;                 // [128][132]

    const int tid  = threadIdx.x;
    const int lane = tid & 31;
    const int wid  = tid >> 5;
    const int tx   = tid & 15;
    const int ty   = tid >> 4;
    const int i0   = blockIdx.x * TI;
    const int ch   = blockIdx.y;
    const int t0   = ch * TPC;
    const int t1   = (t0 + TPC < NT) ? (t0 + TPC) : NT;
    const unsigned FULL = 0xffffffffu;

    // load i-tile coords (transposed) + sq
    for (int e = tid; e < TI * 4; e += 256) {
        int row = e & 127, k4 = e >> 7;
        int gi = i0 + row;
        float4 v = make_float4(0.f, 0.f, 0.f, 0.f);
        if (gi < NPTS) v = ((const float4*)(g_coords + (size_t)gi * DLAT))[k4];
        sA[(4*k4 + 0) * TI + row] = v.x;
        sA[(4*k4 + 1) * TI + row] = v.y;
        sA[(4*k4 + 2) * TI + row] = v.z;
        sA[(4*k4 + 3) * TI + row] = v.w;
    }
    for (int e = tid; e < TI; e += 256) {
        int gi = i0 + e;
        sqI[e] = (gi < NPTS) ? g_sq[gi] : finf();
    }

    // per-warp distributed top-16 (lane = rank; lanes 16..31 = overflow)
    float Ld[16]; int Li[16];
    #pragma unroll
    for (int q = 0; q < 16; q++) { Ld[q] = finf(); Li[q] = 0; }

    for (int t = t0; t < t1; t++) {
        const int j0 = t * TJ;
        __syncthreads();   // previous tile's readers done

        // load j-tile coords (transposed, x2) + sq
        for (int e = tid; e < TJ * 4; e += 256) {
            int row = e & 127, k4 = e >> 7;
            int gj = j0 + row;
            float4 v = make_float4(0.f, 0.f, 0.f, 0.f);
            if (gj < NPTS) v = ((const float4*)(g_coords + (size_t)gj * DLAT))[k4];
            sB[(4*k4 + 0) * TJ + row] = 2.f * v.x;
            sB[(4*k4 + 1) * TJ + row] = 2.f * v.y;
            sB[(4*k4 + 2) * TJ + row] = 2.f * v.z;
            sB[(4*k4 + 3) * TJ + row] = 2.f * v.w;
        }
        for (int e = tid; e < TJ; e += 256) {
            int gj = j0 + e;
            sqJ[e] = (gj < NPTS) ? g_sq[gj] : finf();
        }
        __syncthreads();

        // ---- Phase A: 8x8 register-tiled Gram; d2 into sD2 (R2 layout) ----
        {
            float acc[8][8];
            #pragma unroll
            for (int r = 0; r < 8; r++)
                #pragma unroll
                for (int cc = 0; cc < 8; cc++) acc[r][cc] = 0.f;

            #pragma unroll
            for (int k = 0; k < DLAT; k++) {
                float a[8], b[8];
                #pragma unroll
                for (int rb = 0; rb < 4; rb++) {
                    float2 av = *(const float2*)(sA + k * TI + ty * 2 + rb * 32);
                    a[2*rb] = av.x; a[2*rb+1] = av.y;
                    float2 bv = *(const float2*)(sB + k * TJ + tx * 2 + rb * 32);
                    b[2*rb] = bv.x; b[2*rb+1] = bv.y;
                }
                #pragma unroll
                for (int r = 0; r < 8; r++)
                    #pragma unroll
                    for (int cc = 0; cc < 8; cc++)
                        acc[r][cc] = fmaf(a[r], b[cc], acc[r][cc]);
            }

            float si[8], sj[8];
            #pragma unroll
            for (int rb = 0; rb < 4; rb++) {
                float2 v1 = *(const float2*)(sqI + ty * 2 + rb * 32);
                si[2*rb] = v1.x; si[2*rb+1] = v1.y;
                float2 v2 = *(const float2*)(sqJ + tx * 2 + rb * 32);
                sj[2*rb] = v2.x; sj[2*rb+1] = v2.y;
            }

            // diagonal self-exclusion: irow==col <=> tx==ty && r==c
            const bool diag = (t == (int)blockIdx.x) && (tx == ty);

            #pragma unroll
            for (int r = 0; r < 8; r++) {
                int irow = ty * 2 + (r >> 1) * 32 + (r & 1);
                #pragma unroll
                for (int cb = 0; cb < 4; cb++) {
                    float d0 = fmaxf((si[r] + sj[2*cb])   - acc[r][2*cb],   0.f);
                    float d1 = fmaxf((si[r] + sj[2*cb+1]) - acc[r][2*cb+1], 0.f);
                    if (diag && (r >> 1) == cb) {
                        if ((r & 1) == 0) d0 = finf(); else d1 = finf();
                    }
                    *(float2*)(sD2 + irow * D2S + tx * 2 + cb * 32) = make_float2(d0, d1);
                }
            }
        }
        __syncthreads();

        // ---- Phase B: float4 single-round scan; warp owns queries wid*16..+15 ----
        #pragma unroll
        for (int qi = 0; qi < 16; qi++) {
            const int ql = wid * 16 + qi;
            const int qg = i0 + ql;
            if (qg >= NPTS) continue;               // warp-uniform
            float4 v = *((const float4*)(sD2 + ql * D2S) + lane);  // cols 4*lane..+3
            float thr = __shfl_sync(FULL, Ld[qi], KNN - 1);
            float vmin = fminf(fminf(v.x, v.y), fminf(v.z, v.w));
            unsigned m = __ballot_sync(FULL, vmin < thr);
            while (m) {
                int src = __ffs(m) - 1; m &= m - 1;
                float c0 = __shfl_sync(FULL, v.x, src);
                float c1 = __shfl_sync(FULL, v.y, src);
                float c2 = __shfl_sync(FULL, v.z, src);
                float c3 = __shfl_sync(FULL, v.w, src);
                const int jbase = j0 + 4 * src;
                #pragma unroll
                for (int cc = 0; cc < 4; cc++) {
                    float dd = (cc == 0) ? c0 : (cc == 1) ? c1 : (cc == 2) ? c2 : c3;
                    if (dd < thr) {                 // uniform guard (dd, thr broadcast)
                        float ud = __shfl_up_sync(FULL, Ld[qi], 1);
                        int   ui = __shfl_up_sync(FULL, Li[qi], 1);
                        if (lane == 0) ud = fninf();
                        if (dd < Ld[qi]) {          // strict <: earlier j wins ties
                            bool fu = dd < ud;      // above insertion point: shifted
                            Ld[qi] = fu ? ud : dd;
                            Li[qi] = fu ? ui : (jbase + cc);
                        }
                        thr = __shfl_sync(FULL, Ld[qi], KNN - 1);
                    }
                }
            }
        }
    }

    // write partial lists (lanes 0..15 hold sorted entries)
    #pragma unroll
    for (int qi = 0; qi < 16; qi++) {
        const int qg = i0 + wid * 16 + qi;
        if (qg < NPTS && lane < KNN) {
            g_td[((size_t)qg * NCHUNK + ch) * KNN + lane] = Ld[qi];
            g_ti[((size_t)qg * NCHUNK + ch) * KNN + lane] = Li[qi];
        }
    }
}

// ---------------- kernel 3: merge chunk lists, compute weights ----------------
__global__ void merge_kernel()
{
    const int i = blockIdx.x * blockDim.x + threadIdx.x;
    if (i >= NPTS) return;
    float td[KNN]; int ti[KNN];
    #pragma unroll
    for (int k = 0; k < KNN; k++) { td[k] = finf(); ti[k] = -1; }

    for (int c = 0; c < NCHUNK; c++) {
        const float* sd = g_td + ((size_t)i * NCHUNK + c) * KNN;
        const int*   si = g_ti + ((size_t)i * NCHUNK + c) * KNN;
        for (int k = 0; k < KNN; k++) {
            float dd = sd[k]; int id = si[k];
            if (!(dd < td[KNN - 1])) break;
            #pragma unroll
            for (int q = 0; q < KNN; q++) {
                bool p = dd < td[q];
                float dmin = fminf(dd, td[q]);
                float dmax = fmaxf(dd, td[q]);
                int imin = p ? id : ti[q];
                int imax = p ? ti[q] : id;
                td[q] = dmin; ti[q] = imin;
                dd = dmax; id = imax;
            }
        }
    }
    #pragma unroll
    for (int k = 0; k < KNN; k++) {
        g_w[(size_t)i * KNN + k]   = expf(-td[k]);
        g_idx[(size_t)i * KNN + k] = ti[k];
    }
}

// ---------------- kernel 4: aggregate + concat + final dense (4 q / warp) ----------------
#define OUTQ (8 * QWARP)
__global__ void __launch_bounds__(256) out_kernel(
    const float* __restrict__ Wo, const float* __restrict__ bo,
    float* __restrict__ out)
{
    __shared__ float sW[2 * DFEAT * DFEAT];
    __shared__ float sb[DFEAT];
    __shared__ float scat[OUTQ][2 * DFEAT];

    const int tid = threadIdx.x;
    const float4* Wo4 = (const float4*)Wo;
    float4* sW4 = (float4*)sW;
    for (int e = tid; e < 2 * DFEAT * DFEAT / 4; e += 256) sW4[e] = Wo4[e];
    if (tid < DFEAT) sb[tid] = bo[tid];
    __syncthreads();

    const int w = tid >> 5, lane = tid & 31;
    const int q0 = blockIdx.x * OUTQ + w * QWARP;

    #pragma unroll
    for (int qi = 0; qi < QWARP; qi++) {
        const int q = q0 + qi;
        if (q >= NPTS) break;
        float2 self = ((const float2*)(g_feats + (size_t)q * DFEAT))[lane];
        float a0 = 0.f, a1 = 0.f;
        #pragma unroll
        for (int k = 0; k < KNN; k++) {
            float wk = g_w[(size_t)q * KNN + k];
            int jk = g_idx[(size_t)q * KNN + k];
            float2 fj = ((const float2*)(g_feats + (size_t)jk * DFEAT))[lane];
            a0 = fmaf(wk, fj.x, a0);
            a1 = fmaf(wk, fj.y, a1);
        }
        const int ws = w * QWARP + qi;
        scat[ws][2 * lane]             = self.x;
        scat[ws][2 * lane + 1]         = self.y;
        scat[ws][DFEAT + 2 * lane]     = a0;
        scat[ws][DFEAT + 2 * lane + 1] = a1;
    }
    __syncwarp();

    float o0[QWARP], o1[QWARP];
    float b0 = sb[2 * lane], b1 = sb[2 * lane + 1];
    #pragma unroll
    for (int qi = 0; qi < QWARP; qi++) { o0[qi] = b0; o1[qi] = b1; }

    #pragma unroll 4
    for (int g = 0; g < 2 * DFEAT; g++) {
        float2 ww = ((const float2*)(sW + g * DFEAT))[lane];
        #pragma unroll
        for (int qi = 0; qi < QWARP; qi++) {
            float v = scat[w * QWARP + qi][g];
            o0[qi] = fmaf(v, ww.x, o0[qi]);
            o1[qi] = fmaf(v, ww.y, o1[qi]);
        }
    }
    #pragma unroll
    for (int qi = 0; qi < QWARP; qi++) {
        const int q = q0 + qi;
        if (q < NPTS)
            ((float2*)(out + (size_t)q * DFEAT))[lane] = make_float2(o0[qi], o1[qi]);
    }
}

// ---------------- launch ----------------
extern "C" void kernel_launch(void* const* d_in, const int* in_sizes, int n_in,
                              void* d_out, int out_size)
{
    const float* x  = (const float*)d_in[0];
    const float* Wf = (const float*)d_in[1];
    const float* bf = (const float*)d_in[2];
    const float* Wl = (const float*)d_in[3];
    const float* bl = (const float*)d_in[4];
    const float* Wo = (const float*)d_in[5];
    const float* bo = (const float*)d_in[6];
    float* out = (float*)d_out;

    static int smem_set = 0;
    if (!smem_set) {
        cudaFuncSetAttribute(select_kernel,
                             cudaFuncAttributeMaxDynamicSharedMemorySize, SMEM_SEL);
        smem_set = 1;
    }

    encode_kernel<<<(NPTS + 63) / 64, 64>>>(x, Wf, bf, Wl, bl);
    select_kernel<<<dim3((NPTS + TI - 1) / TI, NCHUNK), 256, SMEM_SEL>>>();
    merge_kernel<<<(NPTS + 127) / 128, 128>>>();
    out_kernel<<<(NPTS + OUTQ - 1) / OUTQ, 256>>>(Wo, bo, out);
}

// round 15
// speedup vs baseline: 1.2613x; 1.2613x over previous
#include <cuda_runtime.h>

#define NPTS  12000
#define DIN   64
#define DLAT  16
#define DFEAT 64
#define KNN   16
#define NCHUNK 3
#define TI    128          // i-tile (queries per block)
#define TJ    128          // j-tile
#define NT    94           // ceil(NPTS/TJ)
#define TPC   32           // tiles per chunk (last chunk: 30)
#define D2S   (TJ + 4)     // padded d2 row stride (words)
#define QWARP 4            // queries per warp in out_kernel

// select smem: sA + sB + sqI + sqJ + sD2
#define SMEM_SEL ((2 * DLAT * TI + 2 * TI + TI * D2S) * 4)

// ---------------- scratch ----------------
__device__ float g_coords[NPTS * DLAT];
__device__ float g_sq[NPTS];
__device__ float g_feats[NPTS * DFEAT];
__device__ float g_td[NPTS * NCHUNK * KNN];
__device__ int   g_ti[NPTS * NCHUNK * KNN];
__device__ float g_w[NPTS * KNN];
__device__ int   g_idx[NPTS * KNN];

__device__ __forceinline__ float finf()  { return __int_as_float(0x7f800000); }
__device__ __forceinline__ float fninf() { return __int_as_float(0xff800000); }

// ---------------- kernel 1: encoders ----------------
__global__ void __launch_bounds__(64) encode_kernel(
    const float* __restrict__ x,
    const float* __restrict__ Wf, const float* __restrict__ bf,
    const float* __restrict__ Wl, const float* __restrict__ bl)
{
    __shared__ float sxT[DIN * 64];
    __shared__ float sWf[DIN * DFEAT];
    __shared__ float sWl[DIN * DLAT];
    __shared__ float sbf[DFEAT];
    __shared__ float sbl[DLAT];

    const int tid = threadIdx.x;
    const int i0  = blockIdx.x * 64;

    for (int e = tid; e < DIN * DFEAT; e += 64) sWf[e] = Wf[e];
    for (int e = tid; e < DIN * DLAT;  e += 64) sWl[e] = Wl[e];
    if (tid < DFEAT) sbf[tid] = bf[tid];
    if (tid < DLAT)  sbl[tid] = bl[tid];

    const float4* x4 = (const float4*)x;
    for (int e = tid; e < 64 * (DIN / 4); e += 64) {
        int r = e >> 4, c4 = e & 15;
        float4 v = make_float4(0.f, 0.f, 0.f, 0.f);
        if (i0 + r < NPTS) v = x4[(size_t)(i0 + r) * (DIN / 4) + c4];
        sxT[(4 * c4 + 0) * 64 + r] = v.x;
        sxT[(4 * c4 + 1) * 64 + r] = v.y;
        sxT[(4 * c4 + 2) * 64 + r] = v.z;
        sxT[(4 * c4 + 3) * 64 + r] = v.w;
    }
    __syncthreads();

    const int i = i0 + tid;
    if (i >= NPTS) return;

    for (int ft = 0; ft < DFEAT; ft += 16) {
        float acc[16];
        #pragma unroll
        for (int f = 0; f < 16; f++) acc[f] = sbf[ft + f];
        #pragma unroll 4
        for (int k = 0; k < DIN; k++) {
            float xv = sxT[k * 64 + tid];
            const float4* wr = (const float4*)(sWf + k * DFEAT + ft);
            #pragma unroll
            for (int q = 0; q < 4; q++) {
                float4 w = wr[q];
                acc[4*q+0] = fmaf(xv, w.x, acc[4*q+0]);
                acc[4*q+1] = fmaf(xv, w.y, acc[4*q+1]);
                acc[4*q+2] = fmaf(xv, w.z, acc[4*q+2]);
                acc[4*q+3] = fmaf(xv, w.w, acc[4*q+3]);
            }
        }
        float4* fo = (float4*)(g_feats + (size_t)i * DFEAT + ft);
        #pragma unroll
        for (int q = 0; q < 4; q++)
            fo[q] = make_float4(tanhf(acc[4*q+0]), tanhf(acc[4*q+1]),
                                tanhf(acc[4*q+2]), tanhf(acc[4*q+3]));
    }

    {
        float acc[16];
        #pragma unroll
        for (int f = 0; f < 16; f++) acc[f] = sbl[f];
        #pragma unroll 4
        for (int k = 0; k < DIN; k++) {
            float xv = sxT[k * 64 + tid];
            const float4* wr = (const float4*)(sWl + k * DLAT);
            #pragma unroll
            for (int q = 0; q < 4; q++) {
                float4 w = wr[q];
                acc[4*q+0] = fmaf(xv, w.x, acc[4*q+0]);
                acc[4*q+1] = fmaf(xv, w.y, acc[4*q+1]);
                acc[4*q+2] = fmaf(xv, w.z, acc[4*q+2]);
                acc[4*q+3] = fmaf(xv, w.w, acc[4*q+3]);
            }
        }
        float sq = 0.f;
        float4* co = (float4*)(g_coords + (size_t)i * DLAT);
        #pragma unroll
        for (int q = 0; q < 4; q++) {
            float t0 = tanhf(acc[4*q+0]);
            float t1 = tanhf(acc[4*q+1]);
            float t2 = tanhf(acc[4*q+2]);
            float t3 = tanhf(acc[4*q+3]);
            co[q] = make_float4(t0, t1, t2, t3);
            sq += t0*t0 + t1*t1 + t2*t2 + t3*t3;
        }
        g_sq[i] = sq;
    }
}

// ---------------- kernel 2: R2 tiled distance GEMM + warp-cooperative top-16 ----------------
__global__ void __launch_bounds__(256, 2) select_kernel()
{
    extern __shared__ float sm[];
    float* sA  = sm;                       // [16][128] coords_i transposed
    float* sB  = sm + DLAT * TI;           // [16][128] 2*coords_j transposed
    float* sqI = sm + 2 * DLAT * TI;       // [128]
    float* sqJ = sqI + TI;                 // [128]
    float* sD2 = sqJ + TJ;                 // [128][132]

    const int tid  = threadIdx.x;
    const int lane = tid & 31;
    const int wid  = tid >> 5;
    const int tx   = tid & 15;
    const int ty   = tid >> 4;
    const int i0   = blockIdx.x * TI;
    const int ch   = blockIdx.y;
    const int t0   = ch * TPC;
    const int t1   = (t0 + TPC < NT) ? (t0 + TPC) : NT;
    const unsigned FULL = 0xffffffffu;

    // load i-tile coords (transposed) + sq
    for (int e = tid; e < TI * 4; e += 256) {
        int row = e & 127, k4 = e >> 7;
        int gi = i0 + row;
        float4 v = make_float4(0.f, 0.f, 0.f, 0.f);
        if (gi < NPTS) v = ((const float4*)(g_coords + (size_t)gi * DLAT))[k4];
        sA[(4*k4 + 0) * TI + row] = v.x;
        sA[(4*k4 + 1) * TI + row] = v.y;
        sA[(4*k4 + 2) * TI + row] = v.z;
        sA[(4*k4 + 3) * TI + row] = v.w;
    }
    for (int e = tid; e < TI; e += 256) {
        int gi = i0 + e;
        sqI[e] = (gi < NPTS) ? g_sq[gi] : finf();
    }

    // per-warp distributed top-16 lists: lane l holds rank-l entry of each of
    // the warp's 16 queries
    float Ld[16]; int Li[16];
    #pragma unroll
    for (int q = 0; q < 16; q++) { Ld[q] = finf(); Li[q] = 0; }

    for (int t = t0; t < t1; t++) {
        const int j0 = t * TJ;
        __syncthreads();   // previous tile's B readers done

        // load j-tile coords (transposed, x2) + sq
        for (int e = tid; e < TJ * 4; e += 256) {
            int row = e & 127, k4 = e >> 7;
            int gj = j0 + row;
            float4 v = make_float4(0.f, 0.f, 0.f, 0.f);
            if (gj < NPTS) v = ((const float4*)(g_coords + (size_t)gj * DLAT))[k4];
            sB[(4*k4 + 0) * TJ + row] = 2.f * v.x;
            sB[(4*k4 + 1) * TJ + row] = 2.f * v.y;
            sB[(4*k4 + 2) * TJ + row] = 2.f * v.z;
            sB[(4*k4 + 3) * TJ + row] = 2.f * v.w;
        }
        for (int e = tid; e < TJ; e += 256) {
            int gj = j0 + e;
            sqJ[e] = (gj < NPTS) ? g_sq[gj] : finf();
        }
        __syncthreads();

        // ---- Phase A: 8x8 register-tiled Gram; d2 into sD2 ----
        {
            float acc[8][8];
            #pragma unroll
            for (int r = 0; r < 8; r++)
                #pragma unroll
                for (int cc = 0; cc < 8; cc++) acc[r][cc] = 0.f;

            #pragma unroll
            for (int k = 0; k < DLAT; k++) {
                float a[8], b[8];
                #pragma unroll
                for (int rb = 0; rb < 4; rb++) {
                    float2 av = *(const float2*)(sA + k * TI + ty * 2 + rb * 32);
                    a[2*rb] = av.x; a[2*rb+1] = av.y;
                    float2 bv = *(const float2*)(sB + k * TJ + tx * 2 + rb * 32);
                    b[2*rb] = bv.x; b[2*rb+1] = bv.y;
                }
                #pragma unroll
                for (int r = 0; r < 8; r++)
                    #pragma unroll
                    for (int cc = 0; cc < 8; cc++)
                        acc[r][cc] = fmaf(a[r], b[cc], acc[r][cc]);
            }

            float si[8], sj[8];
            #pragma unroll
            for (int rb = 0; rb < 4; rb++) {
                float2 v1 = *(const float2*)(sqI + ty * 2 + rb * 32);
                si[2*rb] = v1.x; si[2*rb+1] = v1.y;
                float2 v2 = *(const float2*)(sqJ + tx * 2 + rb * 32);
                sj[2*rb] = v2.x; sj[2*rb+1] = v2.y;
            }

            // diagonal self-exclusion (replaces per-candidate j != i in Phase B):
            // row ty*2+(r>>1)*32+(r&1) == col tx*2+cb*32+(c&1)  <=> tx==ty, cb==r>>1, parity equal
            const bool diag = (t == (int)blockIdx.x) && (tx == ty);

            #pragma unroll
            for (int r = 0; r < 8; r++) {
                int irow = ty * 2 + (r >> 1) * 32 + (r & 1);
                #pragma unroll
                for (int cb = 0; cb < 4; cb++) {
                    float d0 = fmaxf((si[r] + sj[2*cb])   - acc[r][2*cb],   0.f);
                    float d1 = fmaxf((si[r] + sj[2*cb+1]) - acc[r][2*cb+1], 0.f);
                    if (diag && (r >> 1) == cb) {
                        if ((r & 1) == 0) d0 = finf(); else d1 = finf();
                    }
                    *(float2*)(sD2 + irow * D2S + tx * 2 + cb * 32) = make_float2(d0, d1);
                }
            }
        }
        __syncthreads();

        // ---- Phase B: warp-cooperative scan; warp owns queries wid*16..+15 ----
        #pragma unroll
        for (int qi = 0; qi < 16; qi++) {
            const int ql = wid * 16 + qi;
            const int qg = i0 + ql;
            if (qg >= NPTS) continue;               // warp-uniform
            const float* row = sD2 + ql * D2S;
            #pragma unroll
            for (int jb = 0; jb < TJ; jb += 32) {
                float v = row[jb + lane];
                float thr = __shfl_sync(FULL, Ld[qi], KNN - 1);
                unsigned m = __ballot_sync(FULL, v < thr);
                while (m) {
                    int src = __ffs(m) - 1; m &= m - 1;
                    float dd = __shfl_sync(FULL, v, src);
                    int   ji = j0 + jb + src;
                    float ud = __shfl_up_sync(FULL, Ld[qi], 1);
                    int   ui = __shfl_up_sync(FULL, Li[qi], 1);
                    if (lane == 0) ud = fninf();
                    if (dd < Ld[qi]) {              // strict <: earlier j wins ties
                        bool fu = dd < ud;          // above insertion point: take shifted
                        Ld[qi] = fu ? ud : dd;
                        Li[qi] = fu ? ui : ji;
                    }
                }
            }
        }
    }

    // write partial lists (lanes 0..15 hold sorted entries)
    #pragma unroll
    for (int qi = 0; qi < 16; qi++) {
        const int qg = i0 + wid * 16 + qi;
        if (qg < NPTS && lane < 16) {
            g_td[((size_t)qg * NCHUNK + ch) * KNN + lane] = Ld[qi];
            g_ti[((size_t)qg * NCHUNK + ch) * KNN + lane] = Li[qi];
        }
    }
}

// ---------------- kernel 3: merge chunk lists, compute weights ----------------
__global__ void merge_kernel()
{
    const int i = blockIdx.x * blockDim.x + threadIdx.x;
    if (i >= NPTS) return;
    float td[KNN]; int ti[KNN];
    #pragma unroll
    for (int k = 0; k < KNN; k++) { td[k] = finf(); ti[k] = -1; }

    for (int c = 0; c < NCHUNK; c++) {
        const float* sd = g_td + ((size_t)i * NCHUNK + c) * KNN;
        const int*   si = g_ti + ((size_t)i * NCHUNK + c) * KNN;
        for (int k = 0; k < KNN; k++) {
            float dd = sd[k]; int id = si[k];
            if (!(dd < td[KNN - 1])) break;   // lists are sorted ascending
            #pragma unroll
            for (int q = 0; q < KNN; q++) {
                bool p = dd < td[q];
                float dmin = fminf(dd, td[q]);
                float dmax = fmaxf(dd, td[q]);
                int imin = p ? id : ti[q];
                int imax = p ? ti[q] : id;
                td[q] = dmin; ti[q] = imin;
                dd = dmax; id = imax;
            }
        }
    }
    #pragma unroll
    for (int k = 0; k < KNN; k++) {
        g_w[(size_t)i * KNN + k]   = expf(-td[k]);   // d2 already clamped >= 0
        g_idx[(size_t)i * KNN + k] = ti[k];
    }
}

// ---------------- kernel 4: aggregate + concat + final dense (4 q / warp) ----------------
#define OUTQ (8 * QWARP)
__global__ void __launch_bounds__(256) out_kernel(
    const float* __restrict__ Wo, const float* __restrict__ bo,
    float* __restrict__ out)
{
    __shared__ float sW[2 * DFEAT * DFEAT];
    __shared__ float sb[DFEAT];
    __shared__ float scat[OUTQ][2 * DFEAT];

    const int tid = threadIdx.x;
    const float4* Wo4 = (const float4*)Wo;
    float4* sW4 = (float4*)sW;
    for (int e = tid; e < 2 * DFEAT * DFEAT / 4; e += 256) sW4[e] = Wo4[e];
    if (tid < DFEAT) sb[tid] = bo[tid];
    __syncthreads();

    const int w = tid >> 5, lane = tid & 31;
    const int q0 = blockIdx.x * OUTQ + w * QWARP;

    #pragma unroll
    for (int qi = 0; qi < QWARP; qi++) {
        const int q = q0 + qi;
        if (q >= NPTS) break;
        float2 self = ((const float2*)(g_feats + (size_t)q * DFEAT))[lane];
        float a0 = 0.f, a1 = 0.f;
        #pragma unroll
        for (int k = 0; k < KNN; k++) {
            float wk = g_w[(size_t)q * KNN + k];
            int jk = g_idx[(size_t)q * KNN + k];
            float2 fj = ((const float2*)(g_feats + (size_t)jk * DFEAT))[lane];
            a0 = fmaf(wk, fj.x, a0);
            a1 = fmaf(wk, fj.y, a1);
        }
        const int ws = w * QWARP + qi;
        scat[ws][2 * lane]             = self.x;
        scat[ws][2 * lane + 1]         = self.y;
        scat[ws][DFEAT + 2 * lane]     = a0;
        scat[ws][DFEAT + 2 * lane + 1] = a1;
    }
    __syncwarp();

    float o0[QWARP], o1[QWARP];
    float b0 = sb[2 * lane], b1 = sb[2 * lane + 1];
    #pragma unroll
    for (int qi = 0; qi < QWARP; qi++) { o0[qi] = b0; o1[qi] = b1; }

    #pragma unroll 4
    for (int g = 0; g < 2 * DFEAT; g++) {
        float2 ww = ((const float2*)(sW + g * DFEAT))[lane];
        #pragma unroll
        for (int qi = 0; qi < QWARP; qi++) {
            float v = scat[w * QWARP + qi][g];
            o0[qi] = fmaf(v, ww.x, o0[qi]);
            o1[qi] = fmaf(v, ww.y, o1[qi]);
        }
    }
    #pragma unroll
    for (int qi = 0; qi < QWARP; qi++) {
        const int q = q0 + qi;
        if (q < NPTS)
            ((float2*)(out + (size_t)q * DFEAT))[lane] = make_float2(o0[qi], o1[qi]);
    }
}

// ---------------- launch ----------------
extern "C" void kernel_launch(void* const* d_in, const int* in_sizes, int n_in,
                              void* d_out, int out_size)
{
    const float* x  = (const float*)d_in[0];
    const float* Wf = (const float*)d_in[1];
    const float* bf = (const float*)d_in[2];
    const float* Wl = (const float*)d_in[3];
    const float* bl = (const float*)d_in[4];
    const float* Wo = (const float*)d_in[5];
    const float* bo = (const float*)d_in[6];
    float* out = (float*)d_out;

    static int smem_set = 0;
    if (!smem_set) {
        cudaFuncSetAttribute(select_kernel,
                             cudaFuncAttributeMaxDynamicSharedMemorySize, SMEM_SEL);
        smem_set = 1;
    }

    encode_kernel<<<(NPTS + 63) / 64, 64>>>(x, Wf, bf, Wl, bl);
    select_kernel<<<dim3((NPTS + TI - 1) / TI, NCHUNK), 256, SMEM_SEL>>>();
    merge_kernel<<<(NPTS + 127) / 128, 128>>>();
    out_kernel<<<(NPTS + OUTQ - 1) / OUTQ, 256>>>(Wo, bo, out);
}